// round 1
// baseline (speedup 1.0000x reference)
#include <cuda_runtime.h>

// Problem constants
constexpr int Bn  = 2;
constexpr int Tn  = 2048;
constexpr int Cn  = 2048;
constexpr int Hn  = 16;
constexpr int HDn = 128;
constexpr float SCALE = 0.088388347648318447f;   // 1/sqrt(128)
constexpr float EPSv  = 1e-6f;

// Scratch (device globals: allocation-free contract)
__device__ float g_Q[(size_t)Bn * Hn * Tn * HDn];   // [B,H,T,hd]
__device__ float g_K[(size_t)Bn * Hn * Tn * HDn];
__device__ float g_V[(size_t)Bn * Hn * Tn * HDn];
__device__ float g_A[(size_t)Bn * Tn * Cn];         // attention output [B,T,C]

// ---------------------------------------------------------------------------
// GEMM (NT): out[m,n] = sum_k A[m,k] * W[n,k]
// 128x128 tile, BK=16, 256 threads, 8x8 microtile (split 4+4 pattern).
// ---------------------------------------------------------------------------

__global__ __launch_bounds__(256, 1)
void gemm_qkv_kernel(const float* __restrict__ X,
                     const float* __restrict__ Wq,
                     const float* __restrict__ Wk,
                     const float* __restrict__ Wv)
{
    __shared__ float As[16][132];
    __shared__ float Bs[16][132];

    const float* W = (blockIdx.z == 0) ? Wq : (blockIdx.z == 1) ? Wk : Wv;
    float*       O = (blockIdx.z == 0) ? g_Q : (blockIdx.z == 1) ? g_K : g_V;

    const int tid = threadIdx.x;
    const int tx = tid & 15, ty = tid >> 4;
    const int mBase = blockIdx.y * 128;
    const int nBase = blockIdx.x * 128;
    const int K = Cn;

    float acc[8][8];
#pragma unroll
    for (int i = 0; i < 8; i++)
#pragma unroll
        for (int j = 0; j < 8; j++) acc[i][j] = 0.f;

    for (int k0 = 0; k0 < K; k0 += 16) {
#pragma unroll
        for (int l = 0; l < 2; l++) {
            int s   = tid + l * 256;
            int row = s >> 2;
            int cv  = (s & 3) << 2;
            float4 a = *(const float4*)&X[(size_t)(mBase + row) * K + k0 + cv];
            As[cv + 0][row] = a.x; As[cv + 1][row] = a.y;
            As[cv + 2][row] = a.z; As[cv + 3][row] = a.w;
            float4 b = *(const float4*)&W[(size_t)(nBase + row) * K + k0 + cv];
            Bs[cv + 0][row] = b.x; Bs[cv + 1][row] = b.y;
            Bs[cv + 2][row] = b.z; Bs[cv + 3][row] = b.w;
        }
        __syncthreads();
#pragma unroll
        for (int kk = 0; kk < 16; kk++) {
            float a[8], b[8];
            *(float4*)&a[0] = *(const float4*)&As[kk][ty * 4];
            *(float4*)&a[4] = *(const float4*)&As[kk][64 + ty * 4];
            *(float4*)&b[0] = *(const float4*)&Bs[kk][tx * 4];
            *(float4*)&b[4] = *(const float4*)&Bs[kk][64 + tx * 4];
#pragma unroll
            for (int i = 0; i < 8; i++)
#pragma unroll
                for (int j = 0; j < 8; j++)
                    acc[i][j] = fmaf(a[i], b[j], acc[i][j]);
        }
        __syncthreads();
    }

    // Store transposed into [B,H,T,hd]
#pragma unroll
    for (int i = 0; i < 8; i++) {
        int m = mBase + ((i < 4) ? (ty * 4 + i) : (64 + ty * 4 + i - 4));
        int b = m >> 11;               // m / Tn
        int t = m & (Tn - 1);
#pragma unroll
        for (int jg = 0; jg < 2; jg++) {
            int o0 = nBase + jg * 64 + tx * 4;
            int h = o0 >> 7, d = o0 & 127;
            float4 v = *(float4*)&acc[i][jg * 4];
            *(float4*)&O[(size_t)((b * Hn + h) * Tn + t) * HDn + d] = v;
        }
    }
}

__global__ __launch_bounds__(256, 1)
void gemm_out_kernel(const float* __restrict__ Wo, float* __restrict__ Out)
{
    __shared__ float As[16][132];
    __shared__ float Bs[16][132];

    const int tid = threadIdx.x;
    const int tx = tid & 15, ty = tid >> 4;
    const int mBase = blockIdx.y * 128;
    const int nBase = blockIdx.x * 128;
    const int K = Cn;

    float acc[8][8];
#pragma unroll
    for (int i = 0; i < 8; i++)
#pragma unroll
        for (int j = 0; j < 8; j++) acc[i][j] = 0.f;

    for (int k0 = 0; k0 < K; k0 += 16) {
#pragma unroll
        for (int l = 0; l < 2; l++) {
            int s   = tid + l * 256;
            int row = s >> 2;
            int cv  = (s & 3) << 2;
            float4 a = *(const float4*)&g_A[(size_t)(mBase + row) * K + k0 + cv];
            As[cv + 0][row] = a.x; As[cv + 1][row] = a.y;
            As[cv + 2][row] = a.z; As[cv + 3][row] = a.w;
            float4 b = *(const float4*)&Wo[(size_t)(nBase + row) * K + k0 + cv];
            Bs[cv + 0][row] = b.x; Bs[cv + 1][row] = b.y;
            Bs[cv + 2][row] = b.z; Bs[cv + 3][row] = b.w;
        }
        __syncthreads();
#pragma unroll
        for (int kk = 0; kk < 16; kk++) {
            float a[8], b[8];
            *(float4*)&a[0] = *(const float4*)&As[kk][ty * 4];
            *(float4*)&a[4] = *(const float4*)&As[kk][64 + ty * 4];
            *(float4*)&b[0] = *(const float4*)&Bs[kk][tx * 4];
            *(float4*)&b[4] = *(const float4*)&Bs[kk][64 + tx * 4];
#pragma unroll
            for (int i = 0; i < 8; i++)
#pragma unroll
                for (int j = 0; j < 8; j++)
                    acc[i][j] = fmaf(a[i], b[j], acc[i][j]);
        }
        __syncthreads();
    }

#pragma unroll
    for (int i = 0; i < 8; i++) {
        int m = mBase + ((i < 4) ? (ty * 4 + i) : (64 + ty * 4 + i - 4));
#pragma unroll
        for (int jg = 0; jg < 2; jg++) {
            int o0 = nBase + jg * 64 + tx * 4;
            float4 v = *(float4*)&acc[i][jg * 4];
            *(float4*)&Out[(size_t)m * Cn + o0] = v;
        }
    }
}

// ---------------------------------------------------------------------------
// Fused relu-attention. One block: (b,h) x q-tile of 128 rows.
// Iterates 64-row K/V tiles up to the causal boundary.
//   w = relu(q.k*scale + 0.1) masked causal;  out = (w @ v) / (rowsum + eps)
// ---------------------------------------------------------------------------

constexpr int ATTN_SMEM = (128 * 132 + 3 * 64 * 132 + 128) * 4;  // 169472 B

__global__ __launch_bounds__(256, 1)
void attn_kernel()
{
    extern __shared__ float sm[];
    float* Qs     = sm;                  // [128][132]
    float* Ks     = Qs + 128 * 132;      // [64][132]
    float* Vs     = Ks + 64 * 132;       // [64][132]
    float* Wsm    = Vs + 64 * 132;       // [64][132]  Wsm[kcol][qrow]
    float* rowsum = Wsm + 64 * 132;      // [128]

    const int tid = threadIdx.x;
    const int tx = tid & 15, ty = tid >> 4;
    const int qt  = blockIdx.x;
    const int bh  = blockIdx.y;
    const int qg0 = qt * 128;

    const float* Qb = g_Q + ((size_t)bh * Tn + qg0) * HDn;
    const float* Kb = g_K + (size_t)bh * Tn * HDn;
    const float* Vb = g_V + (size_t)bh * Tn * HDn;

    // load Q tile (128 x 128)
#pragma unroll
    for (int l = 0; l < 16; l++) {
        int s  = tid + l * 256;
        int r  = s >> 5;
        int d4 = (s & 31) << 2;
        *(float4*)&Qs[r * 132 + d4] = *(const float4*)&Qb[(size_t)r * HDn + d4];
    }
    if (tid < 128) rowsum[tid] = 0.f;

    float acc[8][8];
#pragma unroll
    for (int i = 0; i < 8; i++)
#pragma unroll
        for (int j = 0; j < 8; j++) acc[i][j] = 0.f;

    int r_[8], c_[8];
#pragma unroll
    for (int i = 0; i < 8; i++) r_[i] = (i < 4) ? (ty * 4 + i) : (64 + ty * 4 + i - 4);
#pragma unroll
    for (int j = 0; j < 8; j++) c_[j] = (j < 4) ? (tx * 4 + j) : (64 + tx * 4 + j - 4);

    const int ktmax = 2 * qt + 1;
    __syncthreads();

    for (int kt = 0; kt <= ktmax; kt++) {
        // load K,V tiles (64 x 128 each)
#pragma unroll
        for (int l = 0; l < 8; l++) {
            int s  = tid + l * 256;
            int r  = s >> 5;
            int d4 = (s & 31) << 2;
            *(float4*)&Ks[r * 132 + d4] = *(const float4*)&Kb[(size_t)(kt * 64 + r) * HDn + d4];
            *(float4*)&Vs[r * 132 + d4] = *(const float4*)&Vb[(size_t)(kt * 64 + r) * HDn + d4];
        }
        __syncthreads();

        // s = q . k  (128x64 tile; this thread: 8 rows x 4 kcols)
        float sv[8][4];
#pragma unroll
        for (int i = 0; i < 8; i++)
#pragma unroll
            for (int j = 0; j < 4; j++) sv[i][j] = 0.f;

#pragma unroll 4
        for (int d = 0; d < 128; d++) {
            float qv[8], kv[4];
#pragma unroll
            for (int i = 0; i < 8; i++) qv[i] = Qs[r_[i] * 132 + d];
#pragma unroll
            for (int j = 0; j < 4; j++) kv[j] = Ks[(tx * 4 + j) * 132 + d];
#pragma unroll
            for (int i = 0; i < 8; i++)
#pragma unroll
                for (int j = 0; j < 4; j++)
                    sv[i][j] = fmaf(qv[i], kv[j], sv[i][j]);
        }

        // relu + causal mask + transpose-store + rowsum
        const bool diag = (kt >= 2 * qt);
#pragma unroll
        for (int i = 0; i < 8; i++) {
            float rs = 0.f;
            int qg = qg0 + r_[i];
#pragma unroll
            for (int j = 0; j < 4; j++) {
                int kg = kt * 64 + tx * 4 + j;
                float w = fmaxf(fmaf(sv[i][j], SCALE, 0.1f), 0.f);
                if (diag && kg > qg) w = 0.f;
                Wsm[(tx * 4 + j) * 132 + r_[i]] = w;
                rs += w;
            }
#pragma unroll
            for (int m = 8; m >= 1; m >>= 1)
                rs += __shfl_xor_sync(0xffffffffu, rs, m);
            if (tx == 0) rowsum[r_[i]] += rs;
        }
        __syncthreads();

        // acc += w @ v   (this thread: 8 rows x 8 dcols)
#pragma unroll 4
        for (int kk = 0; kk < 64; kk++) {
            float wv[8], vv[8];
#pragma unroll
            for (int i = 0; i < 8; i++) wv[i] = Wsm[kk * 132 + r_[i]];
#pragma unroll
            for (int j = 0; j < 8; j++) vv[j] = Vs[kk * 132 + c_[j]];
#pragma unroll
            for (int i = 0; i < 8; i++)
#pragma unroll
                for (int j = 0; j < 8; j++)
                    acc[i][j] = fmaf(wv[i], vv[j], acc[i][j]);
        }
        __syncthreads();
    }

    // normalize + store to [B,T,C]
    const int b = bh >> 4, h = bh & 15;
#pragma unroll
    for (int i = 0; i < 8; i++) {
        int qg = qg0 + r_[i];
        float inv = 1.f / (rowsum[r_[i]] + EPSv);
#pragma unroll
        for (int jg = 0; jg < 2; jg++) {
            int d0 = (jg == 0) ? (tx * 4) : (64 + tx * 4);
            float4 v;
            v.x = acc[i][jg * 4 + 0] * inv;
            v.y = acc[i][jg * 4 + 1] * inv;
            v.z = acc[i][jg * 4 + 2] * inv;
            v.w = acc[i][jg * 4 + 3] * inv;
            *(float4*)&g_A[(size_t)(b * Tn + qg) * Cn + h * 128 + d0] = v;
        }
    }
}

// ---------------------------------------------------------------------------

extern "C" void kernel_launch(void* const* d_in, const int* in_sizes, int n_in,
                              void* d_out, int out_size)
{
    const float* x  = (const float*)d_in[0];
    const float* Wq = (const float*)d_in[1];
    const float* Wk = (const float*)d_in[2];
    const float* Wv = (const float*)d_in[3];
    const float* Wo = (const float*)d_in[4];
    float* out = (float*)d_out;

    cudaFuncSetAttribute(attn_kernel,
                         cudaFuncAttributeMaxDynamicSharedMemorySize, ATTN_SMEM);

    dim3 gProj(Cn / 128, (Bn * Tn) / 128, 3);
    gemm_qkv_kernel<<<gProj, 256>>>(x, Wq, Wk, Wv);

    dim3 gAttn(Tn / 128, Bn * Hn);
    attn_kernel<<<gAttn, 256, ATTN_SMEM>>>();

    dim3 gOut(Cn / 128, (Bn * Tn) / 128);
    gemm_out_kernel<<<gOut, 256>>>(Wo, out);
}

// round 3
// speedup vs baseline: 1.4333x; 1.4333x over previous
#include <cuda_runtime.h>
#include <cuda_bf16.h>

typedef unsigned int       u32;
typedef unsigned long long u64;

// Problem constants
constexpr int Bn  = 2;
constexpr int Tn  = 2048;
constexpr int Cn  = 2048;
constexpr int Hn  = 16;
constexpr int HDn = 128;
constexpr float SCALE = 0.088388347648318447f;   // 1/sqrt(128)
constexpr float EPSv  = 1e-6f;

// ---------------------------------------------------------------------------
// Device-global scratch (allocation-free contract)
// ---------------------------------------------------------------------------
__device__ float g_Q[(size_t)Bn * Hn * Tn * HDn];   // [B,H,T,hd]
__device__ float g_K[(size_t)Bn * Hn * Tn * HDn];
__device__ float g_V[(size_t)Bn * Hn * Tn * HDn];
__device__ float g_A[(size_t)Bn * Tn * Cn];         // attention output [B,T,C]

__device__ __nv_bfloat16 g_Xhi[(size_t)Bn * Tn * Cn];
__device__ __nv_bfloat16 g_Xlo[(size_t)Bn * Tn * Cn];
__device__ __nv_bfloat16 g_Whi[4][(size_t)Cn * Cn];
__device__ __nv_bfloat16 g_Wlo[4][(size_t)Cn * Cn];
__device__ __nv_bfloat16 g_Ahi[(size_t)Bn * Tn * Cn];
__device__ __nv_bfloat16 g_Alo[(size_t)Bn * Tn * Cn];

// ---------------------------------------------------------------------------
// PTX helpers (sm_80-era; compile clean on compute_103 base target)
// ---------------------------------------------------------------------------
__device__ __forceinline__ u32 smem_to_u32(const void* p) {
    u32 a;
    asm("{ .reg .u64 t; cvta.to.shared.u64 t, %1; cvt.u32.u64 %0, t; }"
        : "=r"(a) : "l"(p));
    return a;
}

__device__ __forceinline__ void cp16(u32 saddr, const void* g) {
    asm volatile("cp.async.cg.shared.global [%0], [%1], 16;"
                 :: "r"(saddr), "l"(g) : "memory");
}
#define CP_COMMIT() asm volatile("cp.async.commit_group;" ::: "memory")
#define CP_WAIT(n)  asm volatile("cp.async.wait_group %0;" :: "n"(n) : "memory")

__device__ __forceinline__ void ldsm_x4(u32& r0, u32& r1, u32& r2, u32& r3, u32 addr) {
    asm volatile("ldmatrix.sync.aligned.m8n8.x4.shared.b16 {%0,%1,%2,%3}, [%4];"
                 : "=r"(r0), "=r"(r1), "=r"(r2), "=r"(r3) : "r"(addr));
}
__device__ __forceinline__ void ldsm_x2(u32& r0, u32& r1, u32 addr) {
    asm volatile("ldmatrix.sync.aligned.m8n8.x2.shared.b16 {%0,%1}, [%2];"
                 : "=r"(r0), "=r"(r1) : "r"(addr));
}

__device__ __forceinline__ void mma16816(float* d, const u32* a, const u32* b) {
    asm volatile(
        "mma.sync.aligned.m16n8k16.row.col.f32.bf16.bf16.f32 "
        "{%0,%1,%2,%3}, {%4,%5,%6,%7}, {%8,%9}, {%0,%1,%2,%3};"
        : "+f"(d[0]), "+f"(d[1]), "+f"(d[2]), "+f"(d[3])
        : "r"(a[0]), "r"(a[1]), "r"(a[2]), "r"(a[3]), "r"(b[0]), "r"(b[1]));
}

// ---------------------------------------------------------------------------
// fp32 -> bf16 hi/lo split
// which: 0 = X, 1..4 = Wq,Wk,Wv,Wo, 5 = g_A
// ---------------------------------------------------------------------------
__global__ void split_kernel(const float* __restrict__ in, int which, int n)
{
    int i = (blockIdx.x * blockDim.x + threadIdx.x) * 4;
    if (i >= n) return;

    const float* src = (which == 5) ? g_A : in;
    __nv_bfloat16* hi;
    __nv_bfloat16* lo;
    if (which == 0)      { hi = g_Xhi; lo = g_Xlo; }
    else if (which == 5) { hi = g_Ahi; lo = g_Alo; }
    else                 { hi = g_Whi[which - 1]; lo = g_Wlo[which - 1]; }

    float4 v = *(const float4*)(src + i);
    __nv_bfloat16 h0 = __float2bfloat16(v.x);
    __nv_bfloat16 h1 = __float2bfloat16(v.y);
    __nv_bfloat16 h2 = __float2bfloat16(v.z);
    __nv_bfloat16 h3 = __float2bfloat16(v.w);
    __nv_bfloat16 l0 = __float2bfloat16(v.x - __bfloat162float(h0));
    __nv_bfloat16 l1 = __float2bfloat16(v.y - __bfloat162float(h1));
    __nv_bfloat16 l2 = __float2bfloat16(v.z - __bfloat162float(h2));
    __nv_bfloat16 l3 = __float2bfloat16(v.w - __bfloat162float(h3));

    __nv_bfloat162* hp = (__nv_bfloat162*)(hi + i);
    __nv_bfloat162* lp = (__nv_bfloat162*)(lo + i);
    hp[0] = __halves2bfloat162(h0, h1);
    hp[1] = __halves2bfloat162(h2, h3);
    lp[0] = __halves2bfloat162(l0, l1);
    lp[1] = __halves2bfloat162(l2, l3);
}

// ---------------------------------------------------------------------------
// HMMA bf16-split GEMM:  out[m,n] = sum_k A[m,k] * W[n,k]  (~fp32 precision)
// Block 128x128, BK=32, 8 warps (2x4), warp tile 64x32, m16n8k16 mma,
// double-buffered cp.async, padded smem stride for conflict-free ldmatrix.
// ---------------------------------------------------------------------------
constexpr int GBK     = 32;
constexpr int LDS_H   = 40;                       // smem row stride in halves (32+8)
constexpr int TILE_B  = 128 * LDS_H * 2;          // 10240 B per matrix tile
constexpr int STAGE_B = 4 * TILE_B;               // Ahi/Alo/Bhi/Blo = 40960 B
constexpr int GEMM_SMEM = 2 * STAGE_B;            // 81920 B
constexpr int NCHUNK  = Cn / GBK;                 // 64

__global__ __launch_bounds__(256, 1)
void gemm_bf16(int isOut, float* __restrict__ OutParam)
{
    extern __shared__ char smem[];
    const u32 sbase = smem_to_u32(smem);
    const int tid  = threadIdx.x;
    const int lane = tid & 31;
    const int warp = tid >> 5;
    const int wr   = warp >> 2;     // 0..1 : warp row (64 rows)
    const int wc   = warp & 3;      // 0..3 : warp col (32 cols)

    const int mat = isOut ? 3 : blockIdx.z;
    const __nv_bfloat16* __restrict__ Ahi = isOut ? g_Ahi : g_Xhi;
    const __nv_bfloat16* __restrict__ Alo = isOut ? g_Alo : g_Xlo;
    const __nv_bfloat16* __restrict__ Bhi = g_Whi[mat];
    const __nv_bfloat16* __restrict__ Blo = g_Wlo[mat];

    const int mBase = blockIdx.y * 128;
    const int nBase = blockIdx.x * 128;

    float acc[4][4][4];
#pragma unroll
    for (int i = 0; i < 4; i++)
#pragma unroll
        for (int j = 0; j < 4; j++)
#pragma unroll
            for (int r = 0; r < 4; r++) acc[i][j][r] = 0.f;

    // thread's load slots: 2 rows' halves -> each thread copies 2x16B per tile
    const int ldr = tid >> 1;            // row 0..127
    const int ldc = (tid & 1) * 16;      // half-offset 0 or 16

    auto load_chunk = [&](int kc, int s) {
        const u32 sb = sbase + s * STAGE_B;
        const int k0 = kc * GBK;
        const __nv_bfloat16* srcs[4] = { Ahi, Alo, Bhi, Blo };
        const int rows[4] = { mBase, mBase, nBase, nBase };
#pragma unroll
        for (int t = 0; t < 4; t++) {
            const __nv_bfloat16* g =
                srcs[t] + (size_t)(rows[t] + ldr) * Cn + k0 + ldc;
            u32 sa = sb + t * TILE_B + (ldr * LDS_H + ldc) * 2;
            cp16(sa,      g);
            cp16(sa + 16, g + 8);
        }
        CP_COMMIT();
    };

    load_chunk(0, 0);

    for (int c = 0; c < NCHUNK; c++) {
        const int s = c & 1;
        if (c + 1 < NCHUNK) load_chunk(c + 1, s ^ 1);
        if (c + 1 < NCHUNK) { CP_WAIT(1); } else { CP_WAIT(0); }
        __syncthreads();

        const u32 sb  = sbase + s * STAGE_B;
        const u32 sAh = sb;
        const u32 sAl = sb + TILE_B;
        const u32 sBh = sb + 2 * TILE_B;
        const u32 sBl = sb + 3 * TILE_B;

#pragma unroll
        for (int k16 = 0; k16 < 2; k16++) {
            const int acol = k16 * 16 + (lane >> 4) * 8;     // for x4 (A)
            const int arow = (lane & 15);
            const int bcol = k16 * 16 + ((lane >> 3) & 1) * 8;  // for x2 (B)
            const int brow = (lane & 7);

            u32 ahi[4][4], alo[4][4], bhi[4][2], blo[4][2];
#pragma unroll
            for (int mt = 0; mt < 4; mt++) {
                int row = wr * 64 + mt * 16 + arow;
                u32 off = (u32)(row * LDS_H + acol) * 2;
                ldsm_x4(ahi[mt][0], ahi[mt][1], ahi[mt][2], ahi[mt][3], sAh + off);
                ldsm_x4(alo[mt][0], alo[mt][1], alo[mt][2], alo[mt][3], sAl + off);
            }
#pragma unroll
            for (int nt = 0; nt < 4; nt++) {
                int row = wc * 32 + nt * 8 + brow;
                u32 off = (u32)(row * LDS_H + bcol) * 2;
                ldsm_x2(bhi[nt][0], bhi[nt][1], sBh + off);
                ldsm_x2(blo[nt][0], blo[nt][1], sBl + off);
            }
#pragma unroll
            for (int mt = 0; mt < 4; mt++)
#pragma unroll
                for (int nt = 0; nt < 4; nt++) {
                    mma16816(acc[mt][nt], ahi[mt], bhi[nt]);
                    mma16816(acc[mt][nt], ahi[mt], blo[nt]);
                    mma16816(acc[mt][nt], alo[mt], bhi[nt]);
                }
        }
        __syncthreads();
    }

    // ---- epilogue: acc -> smem -> coalesced gmem
    float* sD = (float*)smem;   // [128][132]
#pragma unroll
    for (int mt = 0; mt < 4; mt++)
#pragma unroll
        for (int nt = 0; nt < 4; nt++) {
            int row = wr * 64 + mt * 16 + (lane >> 2);
            int col = wc * 32 + nt * 8 + (lane & 3) * 2;
            sD[row * 132 + col + 0]       = acc[mt][nt][0];
            sD[row * 132 + col + 1]       = acc[mt][nt][1];
            sD[(row + 8) * 132 + col + 0] = acc[mt][nt][2];
            sD[(row + 8) * 132 + col + 1] = acc[mt][nt][3];
        }
    __syncthreads();

    const int colw = tid & 127;
    const int rh   = tid >> 7;      // 0..1
    if (!isOut) {
        float* O = (mat == 0) ? g_Q : (mat == 1) ? g_K : g_V;
        const int h = blockIdx.x;      // BN == hd == 128
#pragma unroll 4
        for (int rr = 0; rr < 64; rr++) {
            int r = rr * 2 + rh;
            int m = mBase + r;
            int b = m >> 11, t = m & (Tn - 1);
            O[(size_t)((b * Hn + h) * Tn + t) * HDn + colw] = sD[r * 132 + colw];
        }
    } else {
#pragma unroll 4
        for (int rr = 0; rr < 64; rr++) {
            int r = rr * 2 + rh;
            int m = mBase + r;
            OutParam[(size_t)m * Cn + nBase + colw] = sD[r * 132 + colw];
        }
    }
}

// ---------------------------------------------------------------------------
// Fused relu-attention (SIMT fp32, unchanged from R1 — passed at 2.5e-6)
// ---------------------------------------------------------------------------
constexpr int ATTN_SMEM = (128 * 132 + 3 * 64 * 132 + 128) * 4;  // 169472 B

__global__ __launch_bounds__(256, 1)
void attn_kernel()
{
    extern __shared__ float sm[];
    float* Qs     = sm;
    float* Ks     = Qs + 128 * 132;
    float* Vs     = Ks + 64 * 132;
    float* Wsm    = Vs + 64 * 132;
    float* rowsum = Wsm + 64 * 132;

    const int tid = threadIdx.x;
    const int tx = tid & 15, ty = tid >> 4;
    const int qt  = blockIdx.x;
    const int bh  = blockIdx.y;
    const int qg0 = qt * 128;

    const float* Qb = g_Q + ((size_t)bh * Tn + qg0) * HDn;
    const float* Kb = g_K + (size_t)bh * Tn * HDn;
    const float* Vb = g_V + (size_t)bh * Tn * HDn;

#pragma unroll
    for (int l = 0; l < 16; l++) {
        int s  = tid + l * 256;
        int r  = s >> 5;
        int d4 = (s & 31) << 2;
        *(float4*)&Qs[r * 132 + d4] = *(const float4*)&Qb[(size_t)r * HDn + d4];
    }
    if (tid < 128) rowsum[tid] = 0.f;

    float acc[8][8];
#pragma unroll
    for (int i = 0; i < 8; i++)
#pragma unroll
        for (int j = 0; j < 8; j++) acc[i][j] = 0.f;

    int r_[8], c_[8];
#pragma unroll
    for (int i = 0; i < 8; i++) r_[i] = (i < 4) ? (ty * 4 + i) : (64 + ty * 4 + i - 4);
#pragma unroll
    for (int j = 0; j < 8; j++) c_[j] = (j < 4) ? (tx * 4 + j) : (64 + tx * 4 + j - 4);

    const int ktmax = 2 * qt + 1;
    __syncthreads();

    for (int kt = 0; kt <= ktmax; kt++) {
#pragma unroll
        for (int l = 0; l < 8; l++) {
            int s  = tid + l * 256;
            int r  = s >> 5;
            int d4 = (s & 31) << 2;
            *(float4*)&Ks[r * 132 + d4] = *(const float4*)&Kb[(size_t)(kt * 64 + r) * HDn + d4];
            *(float4*)&Vs[r * 132 + d4] = *(const float4*)&Vb[(size_t)(kt * 64 + r) * HDn + d4];
        }
        __syncthreads();

        float sv[8][4];
#pragma unroll
        for (int i = 0; i < 8; i++)
#pragma unroll
            for (int j = 0; j < 4; j++) sv[i][j] = 0.f;

#pragma unroll 4
        for (int d = 0; d < 128; d++) {
            float qv[8], kv[4];
#pragma unroll
            for (int i = 0; i < 8; i++) qv[i] = Qs[r_[i] * 132 + d];
#pragma unroll
            for (int j = 0; j < 4; j++) kv[j] = Ks[(tx * 4 + j) * 132 + d];
#pragma unroll
            for (int i = 0; i < 8; i++)
#pragma unroll
                for (int j = 0; j < 4; j++)
                    sv[i][j] = fmaf(qv[i], kv[j], sv[i][j]);
        }

        const bool diag = (kt >= 2 * qt);
#pragma unroll
        for (int i = 0; i < 8; i++) {
            float rs = 0.f;
            int qg = qg0 + r_[i];
#pragma unroll
            for (int j = 0; j < 4; j++) {
                int kg = kt * 64 + tx * 4 + j;
                float w = fmaxf(fmaf(sv[i][j], SCALE, 0.1f), 0.f);
                if (diag && kg > qg) w = 0.f;
                Wsm[(tx * 4 + j) * 132 + r_[i]] = w;
                rs += w;
            }
#pragma unroll
            for (int m = 8; m >= 1; m >>= 1)
                rs += __shfl_xor_sync(0xffffffffu, rs, m);
            if (tx == 0) rowsum[r_[i]] += rs;
        }
        __syncthreads();

#pragma unroll 4
        for (int kk = 0; kk < 64; kk++) {
            float wv[8], vv[8];
#pragma unroll
            for (int i = 0; i < 8; i++) wv[i] = Wsm[kk * 132 + r_[i]];
#pragma unroll
            for (int j = 0; j < 8; j++) vv[j] = Vs[kk * 132 + c_[j]];
#pragma unroll
            for (int i = 0; i < 8; i++)
#pragma unroll
                for (int j = 0; j < 8; j++)
                    acc[i][j] = fmaf(wv[i], vv[j], acc[i][j]);
        }
        __syncthreads();
    }

    const int b = bh >> 4, h = bh & 15;
#pragma unroll
    for (int i = 0; i < 8; i++) {
        int qg = qg0 + r_[i];
        float inv = 1.f / (rowsum[r_[i]] + EPSv);
#pragma unroll
        for (int jg = 0; jg < 2; jg++) {
            int d0 = (jg == 0) ? (tx * 4) : (64 + tx * 4);
            float4 v;
            v.x = acc[i][jg * 4 + 0] * inv;
            v.y = acc[i][jg * 4 + 1] * inv;
            v.z = acc[i][jg * 4 + 2] * inv;
            v.w = acc[i][jg * 4 + 3] * inv;
            *(float4*)&g_A[(size_t)(b * Tn + qg) * Cn + h * 128 + d0] = v;
        }
    }
}

// ---------------------------------------------------------------------------

extern "C" void kernel_launch(void* const* d_in, const int* in_sizes, int n_in,
                              void* d_out, int out_size)
{
    const float* x  = (const float*)d_in[0];
    const float* Wq = (const float*)d_in[1];
    const float* Wk = (const float*)d_in[2];
    const float* Wv = (const float*)d_in[3];
    const float* Wo = (const float*)d_in[4];
    float* out = (float*)d_out;

    cudaFuncSetAttribute(gemm_bf16,
                         cudaFuncAttributeMaxDynamicSharedMemorySize, GEMM_SMEM);
    cudaFuncSetAttribute(attn_kernel,
                         cudaFuncAttributeMaxDynamicSharedMemorySize, ATTN_SMEM);

    const int nX = Bn * Tn * Cn;   // 8388608
    const int nW = Cn * Cn;        // 4194304

    split_kernel<<<(nX / 4 + 255) / 256, 256>>>(x,  0, nX);
    split_kernel<<<(nW / 4 + 255) / 256, 256>>>(Wq, 1, nW);
    split_kernel<<<(nW / 4 + 255) / 256, 256>>>(Wk, 2, nW);
    split_kernel<<<(nW / 4 + 255) / 256, 256>>>(Wv, 3, nW);
    split_kernel<<<(nW / 4 + 255) / 256, 256>>>(Wo, 4, nW);

    dim3 gQKV(Cn / 128, (Bn * Tn) / 128, 3);
    gemm_bf16<<<gQKV, 256, GEMM_SMEM>>>(0, nullptr);

    dim3 gAttn(Tn / 128, Bn * Hn);
    attn_kernel<<<gAttn, 256, ATTN_SMEM>>>();

    split_kernel<<<(nX / 4 + 255) / 256, 256>>>(nullptr, 5, nX);

    dim3 gOut(Cn / 128, (Bn * Tn) / 128, 1);
    gemm_bf16<<<gOut, 256, GEMM_SMEM>>>(1, out);
}

// round 5
// speedup vs baseline: 2.2883x; 1.5965x over previous
#include <cuda_runtime.h>
#include <cuda_bf16.h>
#include <cuda_fp16.h>

typedef unsigned int       u32;
typedef unsigned long long u64;

// Problem constants
constexpr int Bn  = 2;
constexpr int Tn  = 2048;
constexpr int Cn  = 2048;
constexpr int Hn  = 16;
constexpr int HDn = 128;
constexpr float SCALE = 0.088388347648318447f;   // 1/sqrt(128)
constexpr float EPSv  = 1e-6f;

// ---------------------------------------------------------------------------
// Device-global scratch
// ---------------------------------------------------------------------------
__device__ __nv_bfloat16 g_Qhi[(size_t)Bn * Hn * Tn * HDn];  // [B,H,T,hd]
__device__ __nv_bfloat16 g_Qlo[(size_t)Bn * Hn * Tn * HDn];
__device__ __nv_bfloat16 g_Khi[(size_t)Bn * Hn * Tn * HDn];
__device__ __nv_bfloat16 g_Klo[(size_t)Bn * Hn * Tn * HDn];
__device__ __half        g_Vh [(size_t)Bn * Hn * Tn * HDn];

__device__ __nv_bfloat16 g_Xhi[(size_t)Bn * Tn * Cn];
__device__ __nv_bfloat16 g_Xlo[(size_t)Bn * Tn * Cn];
__device__ __nv_bfloat16 g_Whi[4][(size_t)Cn * Cn];
__device__ __nv_bfloat16 g_Wlo[4][(size_t)Cn * Cn];
__device__ __nv_bfloat16 g_Ahi[(size_t)Bn * Tn * Cn];       // attn out hi/lo
__device__ __nv_bfloat16 g_Alo[(size_t)Bn * Tn * Cn];

// ---------------------------------------------------------------------------
// PTX helpers
// ---------------------------------------------------------------------------
__device__ __forceinline__ u32 smem_to_u32(const void* p) {
    u32 a;
    asm("{ .reg .u64 t; cvta.to.shared.u64 t, %1; cvt.u32.u64 %0, t; }"
        : "=r"(a) : "l"(p));
    return a;
}

__device__ __forceinline__ void cp16(u32 saddr, const void* g) {
    asm volatile("cp.async.cg.shared.global [%0], [%1], 16;"
                 :: "r"(saddr), "l"(g) : "memory");
}
#define CP_COMMIT() asm volatile("cp.async.commit_group;" ::: "memory")
#define CP_WAIT(n)  asm volatile("cp.async.wait_group %0;" :: "n"(n) : "memory")

__device__ __forceinline__ void ldsm_x4(u32& r0, u32& r1, u32& r2, u32& r3, u32 addr) {
    asm volatile("ldmatrix.sync.aligned.m8n8.x4.shared.b16 {%0,%1,%2,%3}, [%4];"
                 : "=r"(r0), "=r"(r1), "=r"(r2), "=r"(r3) : "r"(addr));
}
__device__ __forceinline__ void ldsm_x4_t(u32& r0, u32& r1, u32& r2, u32& r3, u32 addr) {
    asm volatile("ldmatrix.sync.aligned.m8n8.x4.trans.shared.b16 {%0,%1,%2,%3}, [%4];"
                 : "=r"(r0), "=r"(r1), "=r"(r2), "=r"(r3) : "r"(addr));
}
__device__ __forceinline__ void ldsm_x2(u32& r0, u32& r1, u32 addr) {
    asm volatile("ldmatrix.sync.aligned.m8n8.x2.shared.b16 {%0,%1}, [%2];"
                 : "=r"(r0), "=r"(r1) : "r"(addr));
}

__device__ __forceinline__ void mma16816(float* d, const u32* a, const u32* b) {
    asm volatile(
        "mma.sync.aligned.m16n8k16.row.col.f32.bf16.bf16.f32 "
        "{%0,%1,%2,%3}, {%4,%5,%6,%7}, {%8,%9}, {%0,%1,%2,%3};"
        : "+f"(d[0]), "+f"(d[1]), "+f"(d[2]), "+f"(d[3])
        : "r"(a[0]), "r"(a[1]), "r"(a[2]), "r"(a[3]), "r"(b[0]), "r"(b[1]));
}
__device__ __forceinline__ void mma16816h(float* d, const u32* a, const u32* b) {
    asm volatile(
        "mma.sync.aligned.m16n8k16.row.col.f32.f16.f16.f32 "
        "{%0,%1,%2,%3}, {%4,%5,%6,%7}, {%8,%9}, {%0,%1,%2,%3};"
        : "+f"(d[0]), "+f"(d[1]), "+f"(d[2]), "+f"(d[3])
        : "r"(a[0]), "r"(a[1]), "r"(a[2]), "r"(a[3]), "r"(b[0]), "r"(b[1]));
}

// pack {lo, hi} floats (lo -> bits[15:0])
__device__ __forceinline__ u32 pack_bf16x2(float lo, float hi) {
    u32 r;
    asm("cvt.rn.bf16x2.f32 %0, %1, %2;" : "=r"(r) : "f"(hi), "f"(lo));
    return r;
}
__device__ __forceinline__ u32 pack_f16x2(float lo, float hi) {
    u32 r;
    asm("cvt.rn.f16x2.f32 %0, %1, %2;" : "=r"(r) : "f"(hi), "f"(lo));
    return r;
}

// ---------------------------------------------------------------------------
// fp32 -> bf16 hi/lo split.  which: 0 = X, 1..4 = Wq,Wk,Wv,Wo
// ---------------------------------------------------------------------------
__global__ void split_kernel(const float* __restrict__ in, int which, int n)
{
    int i = (blockIdx.x * blockDim.x + threadIdx.x) * 4;
    if (i >= n) return;

    __nv_bfloat16* hi;
    __nv_bfloat16* lo;
    if (which == 0) { hi = g_Xhi; lo = g_Xlo; }
    else            { hi = g_Whi[which - 1]; lo = g_Wlo[which - 1]; }

    float4 v = *(const float4*)(in + i);
    __nv_bfloat16 h0 = __float2bfloat16(v.x);
    __nv_bfloat16 h1 = __float2bfloat16(v.y);
    __nv_bfloat16 h2 = __float2bfloat16(v.z);
    __nv_bfloat16 h3 = __float2bfloat16(v.w);
    __nv_bfloat16 l0 = __float2bfloat16(v.x - __bfloat162float(h0));
    __nv_bfloat16 l1 = __float2bfloat16(v.y - __bfloat162float(h1));
    __nv_bfloat16 l2 = __float2bfloat16(v.z - __bfloat162float(h2));
    __nv_bfloat16 l3 = __float2bfloat16(v.w - __bfloat162float(h3));

    __nv_bfloat162* hp = (__nv_bfloat162*)(hi + i);
    __nv_bfloat162* lp = (__nv_bfloat162*)(lo + i);
    hp[0] = __halves2bfloat162(h0, h1);
    hp[1] = __halves2bfloat162(h2, h3);
    lp[0] = __halves2bfloat162(l0, l1);
    lp[1] = __halves2bfloat162(l2, l3);
}

// ---------------------------------------------------------------------------
// HMMA bf16-split GEMM (~fp32 precision), 128x128 block, BK=32, 8 warps.
// isOut==0: out -> Q/K as hi/lo bf16, V as fp16, all [B,H,T,hd]
// isOut==1: A=attn(hi/lo), B=Wo, out -> fp32 OutParam
// ---------------------------------------------------------------------------
constexpr int GBK     = 32;
constexpr int LDS_H   = 40;
constexpr int TILE_B  = 128 * LDS_H * 2;
constexpr int STAGE_B = 4 * TILE_B;
constexpr int GEMM_SMEM = 2 * STAGE_B;            // 81920 B
constexpr int NCHUNK  = Cn / GBK;                 // 64

__global__ __launch_bounds__(256, 1)
void gemm_bf16(int isOut, float* __restrict__ OutParam)
{
    extern __shared__ char smem[];
    const u32 sbase = smem_to_u32(smem);
    const int tid  = threadIdx.x;
    const int lane = tid & 31;
    const int warp = tid >> 5;
    const int wr   = warp >> 2;
    const int wc   = warp & 3;

    const int mat = isOut ? 3 : blockIdx.z;
    const __nv_bfloat16* __restrict__ Ahi = isOut ? g_Ahi : g_Xhi;
    const __nv_bfloat16* __restrict__ Alo = isOut ? g_Alo : g_Xlo;
    const __nv_bfloat16* __restrict__ Bhi = g_Whi[mat];
    const __nv_bfloat16* __restrict__ Blo = g_Wlo[mat];

    const int mBase = blockIdx.y * 128;
    const int nBase = blockIdx.x * 128;

    float acc[4][4][4];
#pragma unroll
    for (int i = 0; i < 4; i++)
#pragma unroll
        for (int j = 0; j < 4; j++)
#pragma unroll
            for (int r = 0; r < 4; r++) acc[i][j][r] = 0.f;

    const int ldr = tid >> 1;
    const int ldc = (tid & 1) * 16;

    auto load_chunk = [&](int kc, int s) {
        const u32 sb = sbase + s * STAGE_B;
        const int k0 = kc * GBK;
        const __nv_bfloat16* srcs[4] = { Ahi, Alo, Bhi, Blo };
        const int rows[4] = { mBase, mBase, nBase, nBase };
#pragma unroll
        for (int t = 0; t < 4; t++) {
            const __nv_bfloat16* g =
                srcs[t] + (size_t)(rows[t] + ldr) * Cn + k0 + ldc;
            u32 sa = sb + t * TILE_B + (ldr * LDS_H + ldc) * 2;
            cp16(sa,      g);
            cp16(sa + 16, g + 8);
        }
        CP_COMMIT();
    };

    load_chunk(0, 0);

    for (int c = 0; c < NCHUNK; c++) {
        const int s = c & 1;
        if (c + 1 < NCHUNK) load_chunk(c + 1, s ^ 1);
        if (c + 1 < NCHUNK) { CP_WAIT(1); } else { CP_WAIT(0); }
        __syncthreads();

        const u32 sb  = sbase + s * STAGE_B;
        const u32 sAh = sb;
        const u32 sAl = sb + TILE_B;
        const u32 sBh = sb + 2 * TILE_B;
        const u32 sBl = sb + 3 * TILE_B;

#pragma unroll
        for (int k16 = 0; k16 < 2; k16++) {
            const int acol = k16 * 16 + (lane >> 4) * 8;
            const int arow = (lane & 15);
            const int bcol = k16 * 16 + ((lane >> 3) & 1) * 8;
            const int brow = (lane & 7);

            u32 ahi[4][4], alo[4][4], bhi[4][2], blo[4][2];
#pragma unroll
            for (int mt = 0; mt < 4; mt++) {
                int row = wr * 64 + mt * 16 + arow;
                u32 off = (u32)(row * LDS_H + acol) * 2;
                ldsm_x4(ahi[mt][0], ahi[mt][1], ahi[mt][2], ahi[mt][3], sAh + off);
                ldsm_x4(alo[mt][0], alo[mt][1], alo[mt][2], alo[mt][3], sAl + off);
            }
#pragma unroll
            for (int nt = 0; nt < 4; nt++) {
                int row = wc * 32 + nt * 8 + brow;
                u32 off = (u32)(row * LDS_H + bcol) * 2;
                ldsm_x2(bhi[nt][0], bhi[nt][1], sBh + off);
                ldsm_x2(blo[nt][0], blo[nt][1], sBl + off);
            }
#pragma unroll
            for (int mt = 0; mt < 4; mt++)
#pragma unroll
                for (int nt = 0; nt < 4; nt++) {
                    mma16816(acc[mt][nt], ahi[mt], bhi[nt]);
                    mma16816(acc[mt][nt], ahi[mt], blo[nt]);
                    mma16816(acc[mt][nt], alo[mt], bhi[nt]);
                }
        }
        __syncthreads();
    }

    // ---- epilogue
    float* sD = (float*)smem;   // [128][132]
#pragma unroll
    for (int mt = 0; mt < 4; mt++)
#pragma unroll
        for (int nt = 0; nt < 4; nt++) {
            int row = wr * 64 + mt * 16 + (lane >> 2);
            int col = wc * 32 + nt * 8 + (lane & 3) * 2;
            sD[row * 132 + col + 0]       = acc[mt][nt][0];
            sD[row * 132 + col + 1]       = acc[mt][nt][1];
            sD[(row + 8) * 132 + col + 0] = acc[mt][nt][2];
            sD[(row + 8) * 132 + col + 1] = acc[mt][nt][3];
        }
    __syncthreads();

    if (!isOut) {
        const int h  = blockIdx.x;         // BN == hd == 128
        const int c2 = (tid & 63) * 2;
        const int rh = tid >> 6;           // 0..3
#pragma unroll 4
        for (int rr = 0; rr < 32; rr++) {
            int r = rr * 4 + rh;
            int m = mBase + r;
            int b = m >> 11, t = m & (Tn - 1);
            size_t idx = (size_t)((b * Hn + h) * Tn + t) * HDn + c2;
            float v0 = sD[r * 132 + c2];
            float v1 = sD[r * 132 + c2 + 1];
            if (mat == 2) {
                *(u32*)&g_Vh[idx] = pack_f16x2(v0, v1);
            } else {
                float h0 = __bfloat162float(__float2bfloat16(v0));
                float h1 = __bfloat162float(__float2bfloat16(v1));
                __nv_bfloat16* HI = (mat == 0) ? g_Qhi : g_Khi;
                __nv_bfloat16* LO = (mat == 0) ? g_Qlo : g_Klo;
                *(u32*)&HI[idx] = pack_bf16x2(v0, v1);
                *(u32*)&LO[idx] = pack_bf16x2(v0 - h0, v1 - h1);
            }
        }
    } else {
        const int colw = tid & 127;
        const int rh   = tid >> 7;
#pragma unroll 4
        for (int rr = 0; rr < 64; rr++) {
            int r = rr * 2 + rh;
            int m = mBase + r;
            OutParam[(size_t)m * Cn + nBase + colw] = sD[r * 132 + colw];
        }
    }
}

// ---------------------------------------------------------------------------
// HMMA fused relu-attention, split-precision scores.
// S = Qhi*Khi + Qhi*Klo + Qlo*Khi (bf16 3-pass, ~fp32 scores).
// W (fp16) @ V (fp16) single pass.
// Block: 128 q-rows x (b,h). 8 warps x 16 q-rows. 64-row K/V tiles, dbl-buf.
// ---------------------------------------------------------------------------
constexpr int AT_STR  = 136;                              // halves per row
constexpr int AT_Q_B  = 128 * AT_STR * 2;                 // 34816
constexpr int AT_KV_B = 64 * AT_STR * 2;                  // 17408
// layout: Qhi, Qlo, [Kh0, Kl0, V0], [Kh1, Kl1, V1]
constexpr int ATTN_SMEM = 2 * AT_Q_B + 6 * AT_KV_B;       // 174080

__global__ __launch_bounds__(256, 1)
void attn_hmma()
{
    extern __shared__ char smem[];
    const u32 sQh = smem_to_u32(smem);
    const u32 sQl = sQh + AT_Q_B;
    const u32 sS0 = sQl + AT_Q_B;             // stage 0: Kh, Kl, V
    const u32 sS1 = sS0 + 3 * AT_KV_B;        // stage 1

    const int tid  = threadIdx.x;
    const int lane = tid & 31;
    const int w    = tid >> 5;

    const int qt  = (gridDim.x - 1) - blockIdx.x;   // big tiles first
    const int bh  = blockIdx.y;
    const int qg0 = qt * 128;

    const __nv_bfloat16* Qhg = g_Qhi + ((size_t)bh * Tn + qg0) * HDn;
    const __nv_bfloat16* Qlg = g_Qlo + ((size_t)bh * Tn + qg0) * HDn;
    const __nv_bfloat16* Khg = g_Khi + (size_t)bh * Tn * HDn;
    const __nv_bfloat16* Klg = g_Klo + (size_t)bh * Tn * HDn;
    const __half*        Vg  = g_Vh  + (size_t)bh * Tn * HDn;

    auto load_kv = [&](int kt, u32 st) {
        const int kr = tid >> 2, kseg = (tid & 3) * 32;
        const size_t gro = (size_t)(kt * 64 + kr) * HDn;
        const u32 so = (kr * AT_STR + kseg) * 2;
#pragma unroll
        for (int i = 0; i < 4; i++) {
            int c = i * 8;
            cp16(st + so + c * 2,                 Khg + gro + kseg + c);
            cp16(st + AT_KV_B + so + c * 2,       Klg + gro + kseg + c);
            cp16(st + 2 * AT_KV_B + so + c * 2,   Vg  + gro + kseg + c);
        }
        CP_COMMIT();
    };

    // ---- prologue: Q hi/lo + first K/V stage
    {
        const int r = tid >> 1, cseg = (tid & 1) * 64;
#pragma unroll
        for (int i = 0; i < 8; i++) {
            int col = cseg + i * 8;
            cp16(sQh + (r * AT_STR + col) * 2, Qhg + (size_t)r * HDn + col);
            cp16(sQl + (r * AT_STR + col) * 2, Qlg + (size_t)r * HDn + col);
        }
    }
    load_kv(0, sS0);

    const int ktmax = 2 * qt + 1;

    float o[16][4];
#pragma unroll
    for (int i = 0; i < 16; i++)
#pragma unroll
        for (int r = 0; r < 4; r++) o[i][r] = 0.f;
    float rs0 = 0.f, rs1 = 0.f;

    const int r0 = qg0 + w * 16 + (lane >> 2);
    const int r1 = r0 + 8;

    for (int kt = 0; kt <= ktmax; kt++) {
        if (kt + 1 <= ktmax) {
            load_kv(kt + 1, ((kt + 1) & 1) ? sS1 : sS0);
            CP_WAIT(1);
        } else {
            CP_WAIT(0);
        }
        __syncthreads();

        const u32 st  = (kt & 1) ? sS1 : sS0;
        const u32 cKh = st;
        const u32 cKl = st + AT_KV_B;
        const u32 cV  = st + 2 * AT_KV_B;

        // ---- S = Q K^T  3-pass split  (warp: 16 x 64)
        float s[8][4];
#pragma unroll
        for (int i = 0; i < 8; i++)
#pragma unroll
            for (int r = 0; r < 4; r++) s[i][r] = 0.f;

#pragma unroll
        for (int c16 = 0; c16 < 8; c16++) {
            u32 qh[4], ql[4];
            {
                int row = w * 16 + (lane & 15);
                int col = c16 * 16 + (lane >> 4) * 8;
                u32 off = (row * AT_STR + col) * 2;
                ldsm_x4(qh[0], qh[1], qh[2], qh[3], sQh + off);
                ldsm_x4(ql[0], ql[1], ql[2], ql[3], sQl + off);
            }
#pragma unroll
            for (int np = 0; np < 4; np++) {
                int row = np * 16 + (lane & 15);
                int col = c16 * 16 + (lane >> 4) * 8;
                u32 off = (row * AT_STR + col) * 2;
                u32 kh[4], kl[4];
                ldsm_x4(kh[0], kh[1], kh[2], kh[3], cKh + off);
                ldsm_x4(kl[0], kl[1], kl[2], kl[3], cKl + off);
                u32 bh0[2] = { kh[0], kh[2] }, bh1[2] = { kh[1], kh[3] };
                u32 bl0[2] = { kl[0], kl[2] }, bl1[2] = { kl[1], kl[3] };
                mma16816(s[2 * np],     qh, bh0);
                mma16816(s[2 * np + 1], qh, bh1);
                mma16816(s[2 * np],     qh, bl0);
                mma16816(s[2 * np + 1], qh, bl1);
                mma16816(s[2 * np],     ql, bh0);
                mma16816(s[2 * np + 1], ql, bh1);
            }
        }

        // ---- relu + mask + rowsum; pack as fp16 A-frags
        const bool diag = (kt >= 2 * qt);
        u32 wf[4][4];
#pragma unroll
        for (int n8 = 0; n8 < 8; n8++) {
            int kg = kt * 64 + n8 * 8 + (lane & 3) * 2;
            float e0 = fmaxf(fmaf(s[n8][0], SCALE, 0.1f), 0.f);
            float e1 = fmaxf(fmaf(s[n8][1], SCALE, 0.1f), 0.f);
            float e2 = fmaxf(fmaf(s[n8][2], SCALE, 0.1f), 0.f);
            float e3 = fmaxf(fmaf(s[n8][3], SCALE, 0.1f), 0.f);
            if (diag) {
                if (kg     > r0) e0 = 0.f;
                if (kg + 1 > r0) e1 = 0.f;
                if (kg     > r1) e2 = 0.f;
                if (kg + 1 > r1) e3 = 0.f;
            }
            rs0 += e0 + e1;
            rs1 += e2 + e3;
            s[n8][0] = e0; s[n8][1] = e1; s[n8][2] = e2; s[n8][3] = e3;
        }
#pragma unroll
        for (int t = 0; t < 4; t++) {
            wf[t][0] = pack_f16x2(s[2 * t][0],     s[2 * t][1]);
            wf[t][1] = pack_f16x2(s[2 * t][2],     s[2 * t][3]);
            wf[t][2] = pack_f16x2(s[2 * t + 1][0], s[2 * t + 1][1]);
            wf[t][3] = pack_f16x2(s[2 * t + 1][2], s[2 * t + 1][3]);
        }

        // ---- O += W V   (fp16, warp: 16 x 128, k = 64)
#pragma unroll
        for (int t = 0; t < 4; t++) {
#pragma unroll
            for (int d2 = 0; d2 < 8; d2++) {
                u32 vb[4];
                int row = t * 16 + (lane & 15);
                int col = d2 * 16 + (lane >> 4) * 8;
                ldsm_x4_t(vb[0], vb[1], vb[2], vb[3], cV + (row * AT_STR + col) * 2);
                u32 b0[2] = { vb[0], vb[1] };
                u32 b1[2] = { vb[2], vb[3] };
                mma16816h(o[2 * d2],     wf[t], b0);
                mma16816h(o[2 * d2 + 1], wf[t], b1);
            }
        }
        __syncthreads();
    }

    // ---- rowsum reduce, normalize, store hi/lo bf16
    rs0 += __shfl_xor_sync(0xffffffffu, rs0, 1);
    rs0 += __shfl_xor_sync(0xffffffffu, rs0, 2);
    rs1 += __shfl_xor_sync(0xffffffffu, rs1, 1);
    rs1 += __shfl_xor_sync(0xffffffffu, rs1, 2);
    const float inv0 = 1.f / (rs0 + EPSv);
    const float inv1 = 1.f / (rs1 + EPSv);

    const int b  = bh >> 4, hh = bh & 15;
    const size_t base0 = ((size_t)(b * Tn + r0) * Cn) + hh * 128;
    const size_t base1 = ((size_t)(b * Tn + r1) * Cn) + hh * 128;

#pragma unroll
    for (int d8 = 0; d8 < 16; d8++) {
        int col = d8 * 8 + (lane & 3) * 2;
        float v0 = o[d8][0] * inv0, v1 = o[d8][1] * inv0;
        float u0 = o[d8][2] * inv1, u1 = o[d8][3] * inv1;

        float h0 = __bfloat162float(__float2bfloat16(v0));
        float h1 = __bfloat162float(__float2bfloat16(v1));
        float g0 = __bfloat162float(__float2bfloat16(u0));
        float g1 = __bfloat162float(__float2bfloat16(u1));

        *(u32*)&g_Ahi[base0 + col] = pack_bf16x2(v0, v1);
        *(u32*)&g_Alo[base0 + col] = pack_bf16x2(v0 - h0, v1 - h1);
        *(u32*)&g_Ahi[base1 + col] = pack_bf16x2(u0, u1);
        *(u32*)&g_Alo[base1 + col] = pack_bf16x2(u0 - g0, u1 - g1);
    }
}

// ---------------------------------------------------------------------------

extern "C" void kernel_launch(void* const* d_in, const int* in_sizes, int n_in,
                              void* d_out, int out_size)
{
    const float* x  = (const float*)d_in[0];
    const float* Wq = (const float*)d_in[1];
    const float* Wk = (const float*)d_in[2];
    const float* Wv = (const float*)d_in[3];
    const float* Wo = (const float*)d_in[4];
    float* out = (float*)d_out;

    cudaFuncSetAttribute(gemm_bf16,
                         cudaFuncAttributeMaxDynamicSharedMemorySize, GEMM_SMEM);
    cudaFuncSetAttribute(attn_hmma,
                         cudaFuncAttributeMaxDynamicSharedMemorySize, ATTN_SMEM);

    const int nX = Bn * Tn * Cn;
    const int nW = Cn * Cn;

    split_kernel<<<(nX / 4 + 255) / 256, 256>>>(x,  0, nX);
    split_kernel<<<(nW / 4 + 255) / 256, 256>>>(Wq, 1, nW);
    split_kernel<<<(nW / 4 + 255) / 256, 256>>>(Wk, 2, nW);
    split_kernel<<<(nW / 4 + 255) / 256, 256>>>(Wv, 3, nW);
    split_kernel<<<(nW / 4 + 255) / 256, 256>>>(Wo, 4, nW);

    dim3 gQKV(Cn / 128, (Bn * Tn) / 128, 3);
    gemm_bf16<<<gQKV, 256, GEMM_SMEM>>>(0, nullptr);

    dim3 gAttn(Tn / 128, Bn * Hn);
    attn_hmma<<<gAttn, 256, ATTN_SMEM>>>();

    dim3 gOut(Cn / 128, (Bn * Tn) / 128, 1);
    gemm_bf16<<<gOut, 256, GEMM_SMEM>>>(1, out);
}

// round 6
// speedup vs baseline: 3.0645x; 1.3392x over previous
#include <cuda_runtime.h>
#include <cuda_bf16.h>
#include <cuda_fp16.h>

typedef unsigned int       u32;
typedef unsigned long long u64;

// Problem constants
constexpr int Bn  = 2;
constexpr int Tn  = 2048;
constexpr int Cn  = 2048;
constexpr int Hn  = 16;
constexpr int HDn = 128;
constexpr float SCALE = 0.088388347648318447f;   // 1/sqrt(128)
constexpr float EPSv  = 1e-6f;

// ---------------------------------------------------------------------------
// Device-global scratch
// ---------------------------------------------------------------------------
__device__ __nv_bfloat16 g_Qhi[(size_t)Bn * Hn * Tn * HDn];  // [B,H,T,hd]
__device__ __nv_bfloat16 g_Qlo[(size_t)Bn * Hn * Tn * HDn];
__device__ __nv_bfloat16 g_Khi[(size_t)Bn * Hn * Tn * HDn];
__device__ __nv_bfloat16 g_Klo[(size_t)Bn * Hn * Tn * HDn];
__device__ __half        g_Vh [(size_t)Bn * Hn * Tn * HDn];

__device__ __half g_Xhi[(size_t)Bn * Tn * Cn];
__device__ __half g_Xlo[(size_t)Bn * Tn * Cn];
__device__ __half g_Wh[4][(size_t)Cn * Cn];
__device__ __half g_Ahi[(size_t)Bn * Tn * Cn];      // attn out hi/lo fp16
__device__ __half g_Alo[(size_t)Bn * Tn * Cn];

// ---------------------------------------------------------------------------
// PTX helpers
// ---------------------------------------------------------------------------
__device__ __forceinline__ u32 smem_to_u32(const void* p) {
    u32 a;
    asm("{ .reg .u64 t; cvta.to.shared.u64 t, %1; cvt.u32.u64 %0, t; }"
        : "=r"(a) : "l"(p));
    return a;
}

__device__ __forceinline__ void cp16(u32 saddr, const void* g) {
    asm volatile("cp.async.cg.shared.global [%0], [%1], 16;"
                 :: "r"(saddr), "l"(g) : "memory");
}
#define CP_COMMIT() asm volatile("cp.async.commit_group;" ::: "memory")
#define CP_WAIT(n)  asm volatile("cp.async.wait_group %0;" :: "n"(n) : "memory")

__device__ __forceinline__ void ldsm_x4(u32& r0, u32& r1, u32& r2, u32& r3, u32 addr) {
    asm volatile("ldmatrix.sync.aligned.m8n8.x4.shared.b16 {%0,%1,%2,%3}, [%4];"
                 : "=r"(r0), "=r"(r1), "=r"(r2), "=r"(r3) : "r"(addr));
}
__device__ __forceinline__ void ldsm_x4_t(u32& r0, u32& r1, u32& r2, u32& r3, u32 addr) {
    asm volatile("ldmatrix.sync.aligned.m8n8.x4.trans.shared.b16 {%0,%1,%2,%3}, [%4];"
                 : "=r"(r0), "=r"(r1), "=r"(r2), "=r"(r3) : "r"(addr));
}

__device__ __forceinline__ void mma16816(float* d, const u32* a, const u32* b) {
    asm volatile(
        "mma.sync.aligned.m16n8k16.row.col.f32.bf16.bf16.f32 "
        "{%0,%1,%2,%3}, {%4,%5,%6,%7}, {%8,%9}, {%0,%1,%2,%3};"
        : "+f"(d[0]), "+f"(d[1]), "+f"(d[2]), "+f"(d[3])
        : "r"(a[0]), "r"(a[1]), "r"(a[2]), "r"(a[3]), "r"(b[0]), "r"(b[1]));
}
__device__ __forceinline__ void mma16816h(float* d, const u32* a, const u32* b) {
    asm volatile(
        "mma.sync.aligned.m16n8k16.row.col.f32.f16.f16.f32 "
        "{%0,%1,%2,%3}, {%4,%5,%6,%7}, {%8,%9}, {%0,%1,%2,%3};"
        : "+f"(d[0]), "+f"(d[1]), "+f"(d[2]), "+f"(d[3])
        : "r"(a[0]), "r"(a[1]), "r"(a[2]), "r"(a[3]), "r"(b[0]), "r"(b[1]));
}

// pack {lo, hi} floats (lo -> bits[15:0])
__device__ __forceinline__ u32 pack_bf16x2(float lo, float hi) {
    u32 r;
    asm("cvt.rn.bf16x2.f32 %0, %1, %2;" : "=r"(r) : "f"(hi), "f"(lo));
    return r;
}
__device__ __forceinline__ u32 pack_f16x2(float lo, float hi) {
    u32 r;
    asm("cvt.rn.f16x2.f32 %0, %1, %2;" : "=r"(r) : "f"(hi), "f"(lo));
    return r;
}

// ---------------------------------------------------------------------------
// fp32 -> fp16 hi/lo split of X
// ---------------------------------------------------------------------------
__global__ void split_x_kernel(const float* __restrict__ in, int n)
{
    int i = (blockIdx.x * blockDim.x + threadIdx.x) * 4;
    if (i >= n) return;
    float4 v = *(const float4*)(in + i);
    __half h0 = __float2half(v.x), h1 = __float2half(v.y);
    __half h2 = __float2half(v.z), h3 = __float2half(v.w);
    __half l0 = __float2half(v.x - __half2float(h0));
    __half l1 = __float2half(v.y - __half2float(h1));
    __half l2 = __float2half(v.z - __half2float(h2));
    __half l3 = __float2half(v.w - __half2float(h3));
    __half2* hp = (__half2*)(g_Xhi + i);
    __half2* lp = (__half2*)(g_Xlo + i);
    hp[0] = __halves2half2(h0, h1); hp[1] = __halves2half2(h2, h3);
    lp[0] = __halves2half2(l0, l1); lp[1] = __halves2half2(l2, l3);
}

// fp32 -> fp16 single conversion of a weight matrix
__global__ void conv_w_kernel(const float* __restrict__ in, int which, int n)
{
    int i = (blockIdx.x * blockDim.x + threadIdx.x) * 4;
    if (i >= n) return;
    float4 v = *(const float4*)(in + i);
    __half2* p = (__half2*)(g_Wh[which] + i);
    p[0] = __halves2half2(__float2half(v.x), __float2half(v.y));
    p[1] = __halves2half2(__float2half(v.z), __float2half(v.w));
}

// ---------------------------------------------------------------------------
// HMMA fp16 2-pass GEMM:  out[m,n] = sum_k (Ahi+Alo)[m,k] * W[n,k]
// Block 128x128, BK=32, 8 warps (2x4), warp tile 64x32, double-buffered,
// 2 CTAs/SM. Epilogue in two 64-col half passes (fits 61440B smem).
// isOut==0: A=X, B=W[z]; out -> Q/K bf16 hi/lo, V fp16, [B,H,T,hd]
// isOut==1: A=attn out (fp16 hi/lo), B=Wo; out -> fp32 OutParam
// ---------------------------------------------------------------------------
constexpr int GBK     = 32;
constexpr int LDS_H   = 40;
constexpr int TILE_B  = 128 * LDS_H * 2;          // 10240
constexpr int STAGE_B = 3 * TILE_B;               // 30720
constexpr int GEMM_SMEM = 2 * STAGE_B;            // 61440
constexpr int NCHUNK  = Cn / GBK;                 // 64

__global__ __launch_bounds__(256, 2)
void gemm_f16(int isOut, float* __restrict__ OutParam)
{
    extern __shared__ char smem[];
    const u32 sbase = smem_to_u32(smem);
    const int tid  = threadIdx.x;
    const int lane = tid & 31;
    const int warp = tid >> 5;
    const int wr   = warp >> 2;     // 0..1
    const int wc   = warp & 3;      // 0..3

    const int mat = isOut ? 3 : blockIdx.z;
    const __half* __restrict__ Ahi = isOut ? g_Ahi : g_Xhi;
    const __half* __restrict__ Alo = isOut ? g_Alo : g_Xlo;
    const __half* __restrict__ Bm  = g_Wh[mat];

    const int mBase = blockIdx.y * 128;
    const int nBase = blockIdx.x * 128;

    float acc[4][4][4];
#pragma unroll
    for (int i = 0; i < 4; i++)
#pragma unroll
        for (int j = 0; j < 4; j++)
#pragma unroll
            for (int r = 0; r < 4; r++) acc[i][j][r] = 0.f;

    const int ldr = tid >> 1;
    const int ldc = (tid & 1) * 16;

    auto load_chunk = [&](int kc, int s) {
        const u32 sb = sbase + s * STAGE_B;
        const int k0 = kc * GBK;
        const __half* srcs[3] = { Ahi, Alo, Bm };
        const int rows[3] = { mBase, mBase, nBase };
#pragma unroll
        for (int t = 0; t < 3; t++) {
            const __half* g = srcs[t] + (size_t)(rows[t] + ldr) * Cn + k0 + ldc;
            u32 sa = sb + t * TILE_B + (ldr * LDS_H + ldc) * 2;
            cp16(sa,      g);
            cp16(sa + 16, g + 8);
        }
        CP_COMMIT();
    };

    load_chunk(0, 0);

    for (int c = 0; c < NCHUNK; c++) {
        const int s = c & 1;
        if (c + 1 < NCHUNK) load_chunk(c + 1, s ^ 1);
        if (c + 1 < NCHUNK) { CP_WAIT(1); } else { CP_WAIT(0); }
        __syncthreads();

        const u32 sb  = sbase + s * STAGE_B;
        const u32 sAh = sb;
        const u32 sAl = sb + TILE_B;
        const u32 sB  = sb + 2 * TILE_B;

#pragma unroll
        for (int k16 = 0; k16 < 2; k16++) {
            const int col = k16 * 16 + (lane >> 4) * 8;
            const int lrow = (lane & 15);

            u32 ahi[4][4], alo[4][4], bfr[2][4];
#pragma unroll
            for (int mt = 0; mt < 4; mt++) {
                int row = wr * 64 + mt * 16 + lrow;
                u32 off = (u32)(row * LDS_H + col) * 2;
                ldsm_x4(ahi[mt][0], ahi[mt][1], ahi[mt][2], ahi[mt][3], sAh + off);
                ldsm_x4(alo[mt][0], alo[mt][1], alo[mt][2], alo[mt][3], sAl + off);
            }
#pragma unroll
            for (int p = 0; p < 2; p++) {
                int row = wc * 32 + p * 16 + lrow;
                u32 off = (u32)(row * LDS_H + col) * 2;
                ldsm_x4(bfr[p][0], bfr[p][1], bfr[p][2], bfr[p][3], sB + off);
            }
#pragma unroll
            for (int mt = 0; mt < 4; mt++)
#pragma unroll
                for (int p = 0; p < 2; p++) {
                    u32 b0[2] = { bfr[p][0], bfr[p][2] };
                    u32 b1[2] = { bfr[p][1], bfr[p][3] };
                    mma16816h(acc[mt][2 * p],     ahi[mt], b0);
                    mma16816h(acc[mt][2 * p],     alo[mt], b0);
                    mma16816h(acc[mt][2 * p + 1], ahi[mt], b1);
                    mma16816h(acc[mt][2 * p + 1], alo[mt], b1);
                }
        }
        __syncthreads();
    }

    // ---- epilogue: two 64-col half passes through smem
    float* sD = (float*)smem;   // [128][68] = 34816 B
    const int c2  = (tid & 31) * 2;
    const int rr0 = tid >> 5;   // 0..7

#pragma unroll
    for (int hc = 0; hc < 2; hc++) {
        __syncthreads();
        if ((wc >> 1) == hc) {
#pragma unroll
            for (int mt = 0; mt < 4; mt++)
#pragma unroll
                for (int nt = 0; nt < 4; nt++) {
                    int row = wr * 64 + mt * 16 + (lane >> 2);
                    int col = (wc & 1) * 32 + nt * 8 + (lane & 3) * 2;
                    sD[row * 68 + col + 0]       = acc[mt][nt][0];
                    sD[row * 68 + col + 1]       = acc[mt][nt][1];
                    sD[(row + 8) * 68 + col + 0] = acc[mt][nt][2];
                    sD[(row + 8) * 68 + col + 1] = acc[mt][nt][3];
                }
        }
        __syncthreads();

        if (!isOut) {
            const int h = blockIdx.x;
            const int d = hc * 64 + c2;
#pragma unroll 4
            for (int rr = 0; rr < 16; rr++) {
                int r = rr * 8 + rr0;
                int m = mBase + r;
                int b = m >> 11, t = m & (Tn - 1);
                size_t idx = (size_t)((b * Hn + h) * Tn + t) * HDn + d;
                float v0 = sD[r * 68 + c2];
                float v1 = sD[r * 68 + c2 + 1];
                if (mat == 2) {
                    *(u32*)&g_Vh[idx] = pack_f16x2(v0, v1);
                } else {
                    float h0 = __bfloat162float(__float2bfloat16(v0));
                    float h1 = __bfloat162float(__float2bfloat16(v1));
                    __nv_bfloat16* HI = (mat == 0) ? g_Qhi : g_Khi;
                    __nv_bfloat16* LO = (mat == 0) ? g_Qlo : g_Klo;
                    *(u32*)&HI[idx] = pack_bf16x2(v0, v1);
                    *(u32*)&LO[idx] = pack_bf16x2(v0 - h0, v1 - h1);
                }
            }
        } else {
#pragma unroll 4
            for (int rr = 0; rr < 16; rr++) {
                int r = rr * 8 + rr0;
                int m = mBase + r;
                float2 v = make_float2(sD[r * 68 + c2], sD[r * 68 + c2 + 1]);
                *(float2*)&OutParam[(size_t)m * Cn + nBase + hc * 64 + c2] = v;
            }
        }
    }
}

// ---------------------------------------------------------------------------
// HMMA fused relu-attention, split-precision scores (unchanged math from R5).
// S = Qhi*Khi + Qhi*Klo + Qlo*Khi (bf16 3-pass). W(fp16) @ V(fp16).
// ---------------------------------------------------------------------------
constexpr int AT_STR  = 136;
constexpr int AT_Q_B  = 128 * AT_STR * 2;                 // 34816
constexpr int AT_KV_B = 64 * AT_STR * 2;                  // 17408
constexpr int ATTN_SMEM = 2 * AT_Q_B + 6 * AT_KV_B;       // 174080

__global__ __launch_bounds__(256, 1)
void attn_hmma()
{
    extern __shared__ char smem[];
    const u32 sQh = smem_to_u32(smem);
    const u32 sQl = sQh + AT_Q_B;
    const u32 sS0 = sQl + AT_Q_B;
    const u32 sS1 = sS0 + 3 * AT_KV_B;

    const int tid  = threadIdx.x;
    const int lane = tid & 31;
    const int w    = tid >> 5;

    const int qt  = (gridDim.x - 1) - blockIdx.x;
    const int bh  = blockIdx.y;
    const int qg0 = qt * 128;

    const __nv_bfloat16* Qhg = g_Qhi + ((size_t)bh * Tn + qg0) * HDn;
    const __nv_bfloat16* Qlg = g_Qlo + ((size_t)bh * Tn + qg0) * HDn;
    const __nv_bfloat16* Khg = g_Khi + (size_t)bh * Tn * HDn;
    const __nv_bfloat16* Klg = g_Klo + (size_t)bh * Tn * HDn;
    const __half*        Vg  = g_Vh  + (size_t)bh * Tn * HDn;

    auto load_kv = [&](int kt, u32 st) {
        const int kr = tid >> 2, kseg = (tid & 3) * 32;
        const size_t gro = (size_t)(kt * 64 + kr) * HDn;
        const u32 so = (kr * AT_STR + kseg) * 2;
#pragma unroll
        for (int i = 0; i < 4; i++) {
            int c = i * 8;
            cp16(st + so + c * 2,               Khg + gro + kseg + c);
            cp16(st + AT_KV_B + so + c * 2,     Klg + gro + kseg + c);
            cp16(st + 2 * AT_KV_B + so + c * 2, Vg  + gro + kseg + c);
        }
        CP_COMMIT();
    };

    {
        const int r = tid >> 1, cseg = (tid & 1) * 64;
#pragma unroll
        for (int i = 0; i < 8; i++) {
            int col = cseg + i * 8;
            cp16(sQh + (r * AT_STR + col) * 2, Qhg + (size_t)r * HDn + col);
            cp16(sQl + (r * AT_STR + col) * 2, Qlg + (size_t)r * HDn + col);
        }
    }
    load_kv(0, sS0);

    const int ktmax = 2 * qt + 1;

    float o[16][4];
#pragma unroll
    for (int i = 0; i < 16; i++)
#pragma unroll
        for (int r = 0; r < 4; r++) o[i][r] = 0.f;
    float rs0 = 0.f, rs1 = 0.f;

    const int r0 = qg0 + w * 16 + (lane >> 2);
    const int r1 = r0 + 8;

    for (int kt = 0; kt <= ktmax; kt++) {
        if (kt + 1 <= ktmax) {
            load_kv(kt + 1, ((kt + 1) & 1) ? sS1 : sS0);
            CP_WAIT(1);
        } else {
            CP_WAIT(0);
        }
        __syncthreads();

        const u32 st  = (kt & 1) ? sS1 : sS0;
        const u32 cKh = st;
        const u32 cKl = st + AT_KV_B;
        const u32 cV  = st + 2 * AT_KV_B;

        float s[8][4];
#pragma unroll
        for (int i = 0; i < 8; i++)
#pragma unroll
            for (int r = 0; r < 4; r++) s[i][r] = 0.f;

#pragma unroll
        for (int c16 = 0; c16 < 8; c16++) {
            u32 qh[4], ql[4];
            {
                int row = w * 16 + (lane & 15);
                int col = c16 * 16 + (lane >> 4) * 8;
                u32 off = (row * AT_STR + col) * 2;
                ldsm_x4(qh[0], qh[1], qh[2], qh[3], sQh + off);
                ldsm_x4(ql[0], ql[1], ql[2], ql[3], sQl + off);
            }
#pragma unroll
            for (int np = 0; np < 4; np++) {
                int row = np * 16 + (lane & 15);
                int col = c16 * 16 + (lane >> 4) * 8;
                u32 off = (row * AT_STR + col) * 2;
                u32 kh[4], kl[4];
                ldsm_x4(kh[0], kh[1], kh[2], kh[3], cKh + off);
                ldsm_x4(kl[0], kl[1], kl[2], kl[3], cKl + off);
                u32 bh0[2] = { kh[0], kh[2] }, bh1[2] = { kh[1], kh[3] };
                u32 bl0[2] = { kl[0], kl[2] }, bl1[2] = { kl[1], kl[3] };
                mma16816(s[2 * np],     qh, bh0);
                mma16816(s[2 * np + 1], qh, bh1);
                mma16816(s[2 * np],     qh, bl0);
                mma16816(s[2 * np + 1], qh, bl1);
                mma16816(s[2 * np],     ql, bh0);
                mma16816(s[2 * np + 1], ql, bh1);
            }
        }

        const bool diag = (kt >= 2 * qt);
        u32 wf[4][4];
#pragma unroll
        for (int n8 = 0; n8 < 8; n8++) {
            int kg = kt * 64 + n8 * 8 + (lane & 3) * 2;
            float e0 = fmaxf(fmaf(s[n8][0], SCALE, 0.1f), 0.f);
            float e1 = fmaxf(fmaf(s[n8][1], SCALE, 0.1f), 0.f);
            float e2 = fmaxf(fmaf(s[n8][2], SCALE, 0.1f), 0.f);
            float e3 = fmaxf(fmaf(s[n8][3], SCALE, 0.1f), 0.f);
            if (diag) {
                if (kg     > r0) e0 = 0.f;
                if (kg + 1 > r0) e1 = 0.f;
                if (kg     > r1) e2 = 0.f;
                if (kg + 1 > r1) e3 = 0.f;
            }
            rs0 += e0 + e1;
            rs1 += e2 + e3;
            s[n8][0] = e0; s[n8][1] = e1; s[n8][2] = e2; s[n8][3] = e3;
        }
#pragma unroll
        for (int t = 0; t < 4; t++) {
            wf[t][0] = pack_f16x2(s[2 * t][0],     s[2 * t][1]);
            wf[t][1] = pack_f16x2(s[2 * t][2],     s[2 * t][3]);
            wf[t][2] = pack_f16x2(s[2 * t + 1][0], s[2 * t + 1][1]);
            wf[t][3] = pack_f16x2(s[2 * t + 1][2], s[2 * t + 1][3]);
        }

#pragma unroll
        for (int t = 0; t < 4; t++) {
#pragma unroll
            for (int d2 = 0; d2 < 8; d2++) {
                u32 vb[4];
                int row = t * 16 + (lane & 15);
                int col = d2 * 16 + (lane >> 4) * 8;
                ldsm_x4_t(vb[0], vb[1], vb[2], vb[3], cV + (row * AT_STR + col) * 2);
                u32 b0[2] = { vb[0], vb[1] };
                u32 b1[2] = { vb[2], vb[3] };
                mma16816h(o[2 * d2],     wf[t], b0);
                mma16816h(o[2 * d2 + 1], wf[t], b1);
            }
        }
        __syncthreads();
    }

    rs0 += __shfl_xor_sync(0xffffffffu, rs0, 1);
    rs0 += __shfl_xor_sync(0xffffffffu, rs0, 2);
    rs1 += __shfl_xor_sync(0xffffffffu, rs1, 1);
    rs1 += __shfl_xor_sync(0xffffffffu, rs1, 2);
    const float inv0 = 1.f / (rs0 + EPSv);
    const float inv1 = 1.f / (rs1 + EPSv);

    const int b  = bh >> 4, hh = bh & 15;
    const size_t base0 = ((size_t)(b * Tn + r0) * Cn) + hh * 128;
    const size_t base1 = ((size_t)(b * Tn + r1) * Cn) + hh * 128;

#pragma unroll
    for (int d8 = 0; d8 < 16; d8++) {
        int col = d8 * 8 + (lane & 3) * 2;
        float v0 = o[d8][0] * inv0, v1 = o[d8][1] * inv0;
        float u0 = o[d8][2] * inv1, u1 = o[d8][3] * inv1;

        float h0 = __half2float(__float2half(v0));
        float h1 = __half2float(__float2half(v1));
        float g0 = __half2float(__float2half(u0));
        float g1 = __half2float(__float2half(u1));

        *(u32*)&g_Ahi[base0 + col] = pack_f16x2(v0, v1);
        *(u32*)&g_Alo[base0 + col] = pack_f16x2(v0 - h0, v1 - h1);
        *(u32*)&g_Ahi[base1 + col] = pack_f16x2(u0, u1);
        *(u32*)&g_Alo[base1 + col] = pack_f16x2(u0 - g0, u1 - g1);
    }
}

// ---------------------------------------------------------------------------

extern "C" void kernel_launch(void* const* d_in, const int* in_sizes, int n_in,
                              void* d_out, int out_size)
{
    const float* x  = (const float*)d_in[0];
    const float* Wq = (const float*)d_in[1];
    const float* Wk = (const float*)d_in[2];
    const float* Wv = (const float*)d_in[3];
    const float* Wo = (const float*)d_in[4];
    float* out = (float*)d_out;

    cudaFuncSetAttribute(gemm_f16,
                         cudaFuncAttributeMaxDynamicSharedMemorySize, GEMM_SMEM);
    cudaFuncSetAttribute(attn_hmma,
                         cudaFuncAttributeMaxDynamicSharedMemorySize, ATTN_SMEM);

    const int nX = Bn * Tn * Cn;
    const int nW = Cn * Cn;

    split_x_kernel<<<(nX / 4 + 255) / 256, 256>>>(x, nX);
    conv_w_kernel<<<(nW / 4 + 255) / 256, 256>>>(Wq, 0, nW);
    conv_w_kernel<<<(nW / 4 + 255) / 256, 256>>>(Wk, 1, nW);
    conv_w_kernel<<<(nW / 4 + 255) / 256, 256>>>(Wv, 2, nW);
    conv_w_kernel<<<(nW / 4 + 255) / 256, 256>>>(Wo, 3, nW);

    dim3 gQKV(Cn / 128, (Bn * Tn) / 128, 3);
    gemm_f16<<<gQKV, 256, GEMM_SMEM>>>(0, nullptr);

    dim3 gAttn(Tn / 128, Bn * Hn);
    attn_hmma<<<gAttn, 256, ATTN_SMEM>>>();

    dim3 gOut(Cn / 128, (Bn * Tn) / 128, 1);
    gemm_f16<<<gOut, 256, GEMM_SMEM>>>(1, out);
}